// round 16
// baseline (speedup 1.0000x reference)
#include <cuda_runtime.h>
#include <cstdint>
#include <math.h>

#define Bdim 2
#define Tdim 2048
#define HID 2048
#define NH 32
#define NKV 8
#define HD 64
#define BT (Bdim * Tdim)   // 4096

typedef unsigned short ushort_t;

// ---------------- scratch (device globals; no allocations allowed) ----------
__device__ __align__(16) ushort_t g_hf [(size_t)BT * HID];
__device__ __align__(16) ushort_t g_wqf[(size_t)NH * HD * HID];
__device__ __align__(16) ushort_t g_wkf[(size_t)NKV * HD * HID];
__device__ __align__(16) ushort_t g_wvf[(size_t)NKV * HD * HID];
__device__ __align__(16) ushort_t g_wof[(size_t)HID * NH * HD];
__device__ __align__(16) ushort_t g_qf[(size_t)Bdim * NH  * Tdim * HD];
__device__ __align__(16) ushort_t g_kf[(size_t)Bdim * NKV * Tdim * HD];
__device__ __align__(16) ushort_t g_vf[(size_t)Bdim * NKV * Tdim * HD];
__device__ __align__(16) ushort_t g_of[(size_t)BT * NH * HD];

// ======================= helpers ============================================
static __device__ __forceinline__ uint32_t smem_u32(const void* p) {
    uint32_t a;
    asm("{ .reg .u64 t; cvta.to.shared.u64 t, %1; cvt.u32.u64 %0, t; }"
        : "=r"(a) : "l"(p));
    return a;
}

static __device__ __forceinline__ void ldm4(uint32_t* r, uint32_t addr) {
    asm volatile("ldmatrix.sync.aligned.m8n8.x4.shared.b16 {%0,%1,%2,%3}, [%4];"
                 : "=r"(r[0]), "=r"(r[1]), "=r"(r[2]), "=r"(r[3]) : "r"(addr));
}

static __device__ __forceinline__ void ldm4t(uint32_t* r, uint32_t addr) {
    asm volatile("ldmatrix.sync.aligned.m8n8.x4.trans.shared.b16 {%0,%1,%2,%3}, [%4];"
                 : "=r"(r[0]), "=r"(r[1]), "=r"(r[2]), "=r"(r[3]) : "r"(addr));
}

static __device__ __forceinline__ void mma16816h(float* c, const uint32_t* a,
                                                 uint32_t b0, uint32_t b1) {
    asm volatile("mma.sync.aligned.m16n8k16.row.col.f32.f16.f16.f32 "
                 "{%0,%1,%2,%3}, {%4,%5,%6,%7}, {%8,%9}, {%0,%1,%2,%3};"
                 : "+f"(c[0]), "+f"(c[1]), "+f"(c[2]), "+f"(c[3])
                 : "r"(a[0]), "r"(a[1]), "r"(a[2]), "r"(a[3]), "r"(b0), "r"(b1));
}

static __device__ __forceinline__ uint32_t pack_f16(float a, float b) {
    uint32_t r;
    asm("cvt.rn.f16x2.f32 %0, %1, %2;" : "=r"(r) : "f"(b), "f"(a));
    return r;
}
static __device__ __forceinline__ ushort_t f16(float x) {
    ushort_t r;
    asm("cvt.rn.f16.f32 %0, %1;" : "=h"(r) : "f"(x));
    return r;
}

static __device__ __forceinline__ float ex2(float x) {
    float r;
    asm("ex2.approx.f32 %0, %1;" : "=f"(r) : "f"(x));
    return r;
}

#define CP_ASYNC(dst, src) \
    asm volatile("cp.async.cg.shared.global [%0], [%1], 16;" \
                 :: "r"(dst), "l"(src) : "memory")
#define CP_COMMIT() asm volatile("cp.async.commit_group;" ::: "memory")
#define CP_WAIT1() asm volatile("cp.async.wait_group 1;" ::: "memory")
#define CP_WAIT0() asm volatile("cp.async.wait_group 0;" ::: "memory")

// ---------------- merged fp32 -> fp16 convert --------------------------------
#define CV_N0 (BT * HID / 4)
#define CV_N1 (HID * HID / 4)
#define CV_N2 (NKV * HD * HID / 4)
#define CV_N3 (NKV * HD * HID / 4)
#define CV_N4 (HID * HID / 4)
#define CV_TOT (CV_N0 + CV_N1 + CV_N2 + CV_N3 + CV_N4)

__global__ __launch_bounds__(256) void cvt_all(
    const float* __restrict__ h,  const float* __restrict__ wq,
    const float* __restrict__ wk, const float* __restrict__ wv,
    const float* __restrict__ wo) {
    int i = blockIdx.x * blockDim.x + threadIdx.x;
    const float* src;
    ushort_t* dst;
    if (i < CV_N0)                      { src = h;  dst = g_hf; }
    else if ((i -= CV_N0) < CV_N1)      { src = wq; dst = g_wqf; }
    else if ((i -= CV_N1) < CV_N2)      { src = wk; dst = g_wkf; }
    else if ((i -= CV_N2) < CV_N3)      { src = wv; dst = g_wvf; }
    else if ((i -= CV_N3) < CV_N4)      { src = wo; dst = g_wof; }
    else return;
    float4 f = ((const float4*)src)[i];
    ((uint2*)dst)[i] = make_uint2(pack_f16(f.x, f.y), pack_f16(f.z, f.w));
}

// =============== fp16 mma.sync GEMM, k64 chunks, 3-stage pipeline ===========
// MODE 0: O projection, fp32 C store (grid 16x32).
// MODE 1: merged QKV (grid 24x32): x<16 Q(rope+scale), 16-19 K(rope), 20-23 V.
#define G_ROWB 144
#define G_TILE 18432                        // 128 rows x 144 B
#define G_STAGE_B (2 * G_TILE)              // 36864
#define G_SMEM (3 * G_STAGE_B + 128)        // 110720

template<int MODE>
__global__ __launch_bounds__(256, 2) void gemm_fused(
    const ushort_t* __restrict__ A,
    const ushort_t* __restrict__ B1,
    const ushort_t* __restrict__ B2,
    const ushort_t* __restrict__ B3,
    float* __restrict__ C,
    const float* __restrict__ cosp, const float* __restrict__ sinp,
    int K) {
    extern __shared__ char dsm[];
    const uint32_t tile = (smem_u32(dsm) + 127u) & ~127u;

    const int tid = threadIdx.x;
    const int wid = tid >> 5;
    const int lane = tid & 31;
    const int wm = wid & 3;
    const int wn = wid >> 2;

    const bool isQ = (MODE == 0) || (blockIdx.x < 16);
    const bool isV = (MODE == 1) && (blockIdx.x >= 20);
    const int bnx = (MODE == 0) ? (int)blockIdx.x
                   : (blockIdx.x < 16 ? (int)blockIdx.x
                      : (isV ? (int)blockIdx.x - 20 : (int)blockIdx.x - 16));
    const int bm = blockIdx.y * 128;
    const int bn = bnx * 128;
    const ushort_t* Bm = (MODE == 0) ? B1
                        : (blockIdx.x < 16 ? B1 : (isV ? B3 : B2));

    // loader: 2 threads per row, each 32 elements (64 B = 4 x 16B)
    const int row = tid >> 1;
    const int half = tid & 1;
    const ushort_t* pA = A  + (size_t)(bm + row) * K + half * 32;
    const ushort_t* pB = Bm + (size_t)(bn + row) * K + half * 32;
    const uint32_t s_row = (uint32_t)(row * G_ROWB + half * 64);

    const int r8 = lane & 7, sub = lane >> 3;
    const uint32_t a_off = (uint32_t)((wm * 32 + r8 + (sub & 1) * 8) * G_ROWB +
                                      (sub >> 1) * 16);
    const uint32_t b_off = (uint32_t)((wn * 64 + r8 + (sub >> 1) * 8) * G_ROWB +
                                      (sub & 1) * 16);

    float acc[2][8][4];
#pragma unroll
    for (int i = 0; i < 2; i++)
#pragma unroll
        for (int j = 0; j < 8; j++)
#pragma unroll
            for (int q = 0; q < 4; q++) acc[i][j][q] = 0.f;

    const int nch = K >> 6;   // k64 chunks

#define G_ISSUE(chunk, sb) do {                                               \
    const int _k0 = (chunk) << 6;                                             \
    CP_ASYNC((sb) + s_row,               pA + _k0);                           \
    CP_ASYNC((sb) + s_row + 16,          pA + _k0 + 8);                       \
    CP_ASYNC((sb) + s_row + 32,          pA + _k0 + 16);                      \
    CP_ASYNC((sb) + s_row + 48,          pA + _k0 + 24);                      \
    CP_ASYNC((sb) + G_TILE + s_row,      pB + _k0);                           \
    CP_ASYNC((sb) + G_TILE + s_row + 16, pB + _k0 + 8);                       \
    CP_ASYNC((sb) + G_TILE + s_row + 32, pB + _k0 + 16);                      \
    CP_ASYNC((sb) + G_TILE + s_row + 48, pB + _k0 + 24);                      \
} while (0)

    G_ISSUE(0, tile);              CP_COMMIT();
    G_ISSUE(1, tile + G_STAGE_B);  CP_COMMIT();

    int st = 0;                         // i % 3
    for (int i = 0; i < nch; i++) {
        const uint32_t cur = tile + (uint32_t)st * G_STAGE_B;
        if (i + 1 < nch) { CP_WAIT1(); } else { CP_WAIT0(); }
        __syncthreads();
        if (i + 2 < nch) {
            int st2 = st + 2; if (st2 >= 3) st2 -= 3;
            G_ISSUE(i + 2, tile + (uint32_t)st2 * G_STAGE_B);
            CP_COMMIT();
        }

#pragma unroll
        for (int ks = 0; ks < 4; ks++) {
            uint32_t ah[8];
            const uint32_t ka = cur + a_off + ks * 32;
            ldm4(ah,     ka);
            ldm4(ah + 4, ka + 16 * G_ROWB);
#pragma unroll
            for (int g = 0; g < 4; g++) {
                uint32_t bh[4];
                ldm4(bh, cur + G_TILE + b_off + ks * 32 + g * (16 * G_ROWB));
#pragma unroll
                for (int ms = 0; ms < 2; ms++) {
                    mma16816h(acc[ms][2 * g],     ah + 4 * ms, bh[0], bh[1]);
                    mma16816h(acc[ms][2 * g + 1], ah + 4 * ms, bh[2], bh[3]);
                }
            }
        }
        if (++st == 3) st = 0;
    }
#undef G_ISSUE

    // ---------------- epilogues ----------------
    const int trow = lane >> 2;
    const int tcol = (lane & 3) * 2;

    if (MODE == 0) {
#pragma unroll
        for (int ms = 0; ms < 2; ms++) {
#pragma unroll
            for (int nf = 0; nf < 8; nf++) {
                const int r = bm + wm * 32 + ms * 16 + trow;
                const int c = bn + wn * 64 + nf * 8 + tcol;
                *(float2*)(C + (size_t)r * HID + c) =
                    make_float2(acc[ms][nf][0], acc[ms][nf][1]);
                *(float2*)(C + (size_t)(r + 8) * HID + c) =
                    make_float2(acc[ms][nf][2], acc[ms][nf][3]);
            }
        }
    } else {
        const int head = (bn + wn * 64) >> 6;
        const int nheads = isQ ? NH : NKV;
        const float sc = isQ ? (0.125f * 1.4426950408889634f) : 1.0f;
        ushort_t* gf = isQ ? g_qf : (isV ? g_vf : g_kf);
#pragma unroll
        for (int ms = 0; ms < 2; ms++) {
#pragma unroll
            for (int q2 = 0; q2 < 2; q2++) {
                const int token = bm + wm * 32 + ms * 16 + trow + q2 * 8;
                const int bb = token >> 11;
                const int tt = token & (Tdim - 1);
                const size_t obase =
                    ((size_t)(bb * nheads + head) * Tdim + tt) * HD;
                if (isV) {
#pragma unroll
                    for (int nf = 0; nf < 8; nf++) {
#pragma unroll
                        for (int qc = 0; qc < 2; qc++) {
                            const int d = nf * 8 + tcol + qc;
                            gf[obase + d] = f16(acc[ms][nf][q2 * 2 + qc]);
                        }
                    }
                } else {
#pragma unroll
                    for (int nf = 0; nf < 4; nf++) {
#pragma unroll
                        for (int qc = 0; qc < 2; qc++) {
                            const int d = nf * 8 + tcol + qc;   // 0..31
                            float x1 = acc[ms][nf][q2 * 2 + qc];
                            float x2 = acc[ms][nf + 4][q2 * 2 + qc];
                            float c = cosp[(size_t)token * HD + d];
                            float s = sinp[(size_t)token * HD + d];
                            gf[obase + d]      = f16((x1 * c - x2 * s) * sc);
                            gf[obase + d + 32] = f16((x2 * c + x1 * s) * sc);
                        }
                    }
                }
            }
        }
    }
}

// ---------------- Flash attention (fp16, 128-row stages, 2-stage pipeline) --
// Br=128, 256 threads (8 warps). Q resident; K/V staged 128 rows at a time,
// processed as two Bc=64 halves -> one barrier per 128 K-rows.
// smem bytes: Q [0,18432); stage s at 18432 + s*36864: K[128][72] | V[128][72].
#define FB 144
#define FA_SMEM (18432 + 2 * 36864)   // 92160

__global__ __launch_bounds__(256, 2) void flash_mma() {
    extern __shared__ ushort_t fsm[];
    const uint32_t s0 = smem_u32(fsm);
    const uint32_t sQ = s0;

    const int tid = threadIdx.x;
    const int lane = tid & 31;
    const int w = tid >> 5;
    const int qtile = (int)gridDim.x - 1 - (int)blockIdx.x;  // big first
    const int bh = blockIdx.y;
    const int b = bh / NH;
    const int h = bh % NH;
    const int kvh = h / (NH / NKV);

    const ushort_t* qp = g_qf + ((size_t)bh * Tdim + qtile * 128) * HD;
    const size_t kvbase = (size_t)(b * NKV + kvh) * Tdim * HD;
    const ushort_t* pk = g_kf + kvbase;
    const ushort_t* pv = g_vf + kvbase;

    // loader: thread t covers one row of K (t<128) or V (t>=128); 8 x 16B
    const int fa_row = tid & 127;
    const ushort_t* fa_src = (tid < 128) ? pk : pv;
    const uint32_t fa_dst = (uint32_t)(((tid < 128) ? 0 : 18432) + fa_row * FB);
    const uint32_t fa_soff = (uint32_t)(fa_row * HD);

#define FA_ISSUE(s, buf) do {                                                 \
    const uint32_t _sb = s0 + 18432 + (uint32_t)(buf) * 36864 + fa_dst;       \
    const ushort_t* _sp = fa_src + (size_t)(s) * 128 * HD + fa_soff;          \
    CP_ASYNC(_sb,       _sp);                                                 \
    CP_ASYNC(_sb + 16,  _sp + 8);                                             \
    CP_ASYNC(_sb + 32,  _sp + 16);                                            \
    CP_ASYNC(_sb + 48,  _sp + 24);                                            \
    CP_ASYNC(_sb + 64,  _sp + 32);                                            \
    CP_ASYNC(_sb + 80,  _sp + 40);                                            \
    CP_ASYNC(_sb + 96,  _sp + 48);                                            \
    CP_ASYNC(_sb + 112, _sp + 56);                                            \
} while (0)

    FA_ISSUE(0, 0); CP_COMMIT();

    // stage Q (128x64 fp16)
#pragma unroll
    for (int j = 0; j < 4; j++) {
        const int idx = tid + j * 256;
        const int qr = idx >> 3;
        const int qc = idx & 7;
        *(uint4*)(fsm + qr * 72 + qc * 8) = *(const uint4*)(qp + qr * HD + qc * 8);
    }

    const int r8 = lane & 7, sub = lane >> 3;
    const uint32_t a_off = (uint32_t)((w * 16 + r8 + ((sub & 1) << 3)) * FB +
                                      ((sub >> 1) << 4));
    const uint32_t b_off = (uint32_t)((r8 + ((sub >> 1) << 3)) * FB +
                                      ((sub & 1) << 4));
    const uint32_t v_off = (uint32_t)(((lane & 8) + (lane & 7)) * FB +
                                      (lane >> 4) * 16);

    float m0 = -1e30f, m1 = -1e30f, l0 = 0.f, l1 = 0.f;
    float o[8][4];
#pragma unroll
    for (int t = 0; t < 8; t++)
#pragma unroll
        for (int e = 0; e < 4; e++) o[t][e] = 0.f;

    const int ktmax = 2 * qtile + 1;       // last 64-row tile index
    const int nst = qtile + 1;             // number of 128-row stages
    for (int s = 0; s < nst; s++) {
        const uint32_t stg = s0 + 18432 + (uint32_t)(s & 1) * 36864;
        CP_WAIT0();
        __syncthreads();
        if (s + 1 < nst) {
            FA_ISSUE(s + 1, (s + 1) & 1);
            CP_COMMIT();
        }

#pragma unroll
        for (int hh = 0; hh < 2; hh++) {
            const int kt = 2 * s + hh;
            const uint32_t stgK = stg + (uint32_t)hh * 9216;
            const uint32_t stgV = stg + 18432 + (uint32_t)hh * 9216;

            // last 64-tile: warps 0-3 fully above diagonal -> exact no-op
            if (kt == ktmax && w < 4) continue;

            float sa[8][4];
#pragma unroll
            for (int t = 0; t < 8; t++)
#pragma unroll
                for (int e = 0; e < 4; e++) sa[t][e] = 0.f;

#pragma unroll
            for (int ks = 0; ks < 4; ks++) {
                uint32_t aq[4];
                ldm4(aq, sQ + a_off + ks * 32);
#pragma unroll
                for (int g = 0; g < 4; g++) {
                    uint32_t kb[4];
                    ldm4(kb, stgK + b_off + ks * 32 + g * (16 * FB));
                    mma16816h(sa[2 * g],     aq, kb[0], kb[1]);
                    mma16816h(sa[2 * g + 1], aq, kb[2], kb[3]);
                }
            }

            if (kt >= 2 * qtile) {
                const int row0 = qtile * 128 + w * 16 + (lane >> 2);
                const int cb = kt * 64 + (lane & 3) * 2;
#pragma unroll
                for (int t = 0; t < 8; t++) {
                    const int c0 = cb + t * 8;
                    if (c0 > row0)         sa[t][0] = -1e30f;
                    if (c0 + 1 > row0)     sa[t][1] = -1e30f;
                    if (c0 > row0 + 8)     sa[t][2] = -1e30f;
                    if (c0 + 1 > row0 + 8) sa[t][3] = -1e30f;
                }
            }

            float rm0 = -1e30f, rm1 = -1e30f;
#pragma unroll
            for (int t = 0; t < 8; t++) {
                rm0 = fmaxf(rm0, fmaxf(sa[t][0], sa[t][1]));
                rm1 = fmaxf(rm1, fmaxf(sa[t][2], sa[t][3]));
            }
            rm0 = fmaxf(rm0, __shfl_xor_sync(0xffffffffu, rm0, 1));
            rm0 = fmaxf(rm0, __shfl_xor_sync(0xffffffffu, rm0, 2));
            rm1 = fmaxf(rm1, __shfl_xor_sync(0xffffffffu, rm1, 1));
            rm1 = fmaxf(rm1, __shfl_xor_sync(0xffffffffu, rm1, 2));
            const float mn0 = fmaxf(m0, rm0);
            const float mn1 = fmaxf(m1, rm1);
            const float al0 = ex2(m0 - mn0);
            const float al1 = ex2(m1 - mn1);
            m0 = mn0; m1 = mn1;
            float rs0 = 0.f, rs1 = 0.f;
#pragma unroll
            for (int t = 0; t < 8; t++) {
                sa[t][0] = ex2(sa[t][0] - mn0);
                sa[t][1] = ex2(sa[t][1] - mn0);
                sa[t][2] = ex2(sa[t][2] - mn1);
                sa[t][3] = ex2(sa[t][3] - mn1);
                rs0 += sa[t][0] + sa[t][1];
                rs1 += sa[t][2] + sa[t][3];
            }
            rs0 += __shfl_xor_sync(0xffffffffu, rs0, 1);
            rs0 += __shfl_xor_sync(0xffffffffu, rs0, 2);
            rs1 += __shfl_xor_sync(0xffffffffu, rs1, 1);
            rs1 += __shfl_xor_sync(0xffffffffu, rs1, 2);
            l0 = l0 * al0 + rs0;
            l1 = l1 * al1 + rs1;
#pragma unroll
            for (int t = 0; t < 8; t++) {
                o[t][0] *= al0; o[t][1] *= al0;
                o[t][2] *= al1; o[t][3] *= al1;
            }

#pragma unroll
            for (int kc = 0; kc < 4; kc++) {
                const int t0 = 2 * kc, t1 = 2 * kc + 1;
                uint32_t ap[4];
                ap[0] = pack_f16(sa[t0][0], sa[t0][1]);
                ap[1] = pack_f16(sa[t0][2], sa[t0][3]);
                ap[2] = pack_f16(sa[t1][0], sa[t1][1]);
                ap[3] = pack_f16(sa[t1][2], sa[t1][3]);
#pragma unroll
                for (int tp = 0; tp < 4; tp++) {
                    uint32_t vb[4];
                    ldm4t(vb, stgV + v_off + kc * (16 * FB) + tp * 32);
                    mma16816h(o[2 * tp],     ap, vb[0], vb[1]);
                    mma16816h(o[2 * tp + 1], ap, vb[2], vb[3]);
                }
            }
        }
    }
#undef FA_ISSUE

    // epilogue: normalize + fp16 write for the O projection
    const float inv0 = 1.0f / l0;
    const float inv1 = 1.0f / l1;
    const int row0 = qtile * 128 + w * 16 + (lane >> 2);
    const int colb = (lane & 3) * 2;
#pragma unroll
    for (int t = 0; t < 8; t++) {
        const int c = h * HD + t * 8 + colb;
        const size_t i0 = ((size_t)b * Tdim + row0) * (NH * HD) + c;
        const size_t i1 = ((size_t)b * Tdim + row0 + 8) * (NH * HD) + c;
        *(uint32_t*)(g_of + i0) = pack_f16(o[t][0] * inv0, o[t][1] * inv0);
        *(uint32_t*)(g_of + i1) = pack_f16(o[t][2] * inv1, o[t][3] * inv1);
    }
}

// ---------------- launch ----------------------------------------------------
extern "C" void kernel_launch(void* const* d_in, const int* in_sizes, int n_in,
                              void* d_out, int out_size) {
    const float* hidden = (const float*)d_in[0];
    const float* cosp   = (const float*)d_in[1];
    const float* sinp   = (const float*)d_in[2];
    const float* wq     = (const float*)d_in[3];
    const float* wk     = (const float*)d_in[4];
    const float* wv     = (const float*)d_in[5];
    const float* wo     = (const float*)d_in[6];
    float* out = (float*)d_out;

    ushort_t *hf, *wqf, *wkf, *wvf, *wof, *of;
    cudaGetSymbolAddress((void**)&hf,  g_hf);
    cudaGetSymbolAddress((void**)&wqf, g_wqf);
    cudaGetSymbolAddress((void**)&wkf, g_wkf);
    cudaGetSymbolAddress((void**)&wvf, g_wvf);
    cudaGetSymbolAddress((void**)&wof, g_wof);
    cudaGetSymbolAddress((void**)&of,  g_of);

    cudaFuncSetAttribute(gemm_fused<0>, cudaFuncAttributeMaxDynamicSharedMemorySize, G_SMEM);
    cudaFuncSetAttribute(gemm_fused<1>, cudaFuncAttributeMaxDynamicSharedMemorySize, G_SMEM);
    cudaFuncSetAttribute(flash_mma, cudaFuncAttributeMaxDynamicSharedMemorySize, FA_SMEM);

    // merged fp32 -> fp16 converts
    cvt_all<<<(CV_TOT + 255) / 256, 256>>>(hidden, wq, wk, wv, wo);

    // merged Q/K/V projections (Q: rope+scale, K: rope, V: plain) -> fp16
    gemm_fused<1><<<dim3(24, 32), 256, G_SMEM>>>(
        hf, wqf, wkf, wvf, nullptr, cosp, sinp, HID);

    // Flash attention (fp16 tensor cores)
    flash_mma<<<dim3(Tdim / 128, Bdim * NH), 256, FA_SMEM>>>();

    // Output projection (fp16, fp32 epilogue)
    gemm_fused<0><<<dim3(16, 32), 256, G_SMEM>>>(
        of, wof, nullptr, nullptr, out, nullptr, nullptr, HID);
}

// round 17
// speedup vs baseline: 1.1365x; 1.1365x over previous
#include <cuda_runtime.h>
#include <cstdint>
#include <math.h>

#define Bdim 2
#define Tdim 2048
#define HID 2048
#define NH 32
#define NKV 8
#define HD 64
#define BT (Bdim * Tdim)   // 4096

typedef unsigned short ushort_t;

// ---------------- scratch (device globals; no allocations allowed) ----------
__device__ __align__(16) ushort_t g_hf [(size_t)BT * HID];
__device__ __align__(16) ushort_t g_wqf[(size_t)NH * HD * HID];
__device__ __align__(16) ushort_t g_wkf[(size_t)NKV * HD * HID];
__device__ __align__(16) ushort_t g_wvf[(size_t)NKV * HD * HID];
__device__ __align__(16) ushort_t g_wof[(size_t)HID * NH * HD];
__device__ __align__(16) ushort_t g_qf[(size_t)Bdim * NH  * Tdim * HD];
__device__ __align__(16) ushort_t g_kf[(size_t)Bdim * NKV * Tdim * HD];
__device__ __align__(16) ushort_t g_vf[(size_t)Bdim * NKV * Tdim * HD];
__device__ __align__(16) ushort_t g_of[(size_t)BT * NH * HD];

// ======================= helpers ============================================
static __device__ __forceinline__ uint32_t smem_u32(const void* p) {
    uint32_t a;
    asm("{ .reg .u64 t; cvta.to.shared.u64 t, %1; cvt.u32.u64 %0, t; }"
        : "=r"(a) : "l"(p));
    return a;
}

static __device__ __forceinline__ void ldm4(uint32_t* r, uint32_t addr) {
    asm volatile("ldmatrix.sync.aligned.m8n8.x4.shared.b16 {%0,%1,%2,%3}, [%4];"
                 : "=r"(r[0]), "=r"(r[1]), "=r"(r[2]), "=r"(r[3]) : "r"(addr));
}

static __device__ __forceinline__ void ldm4t(uint32_t* r, uint32_t addr) {
    asm volatile("ldmatrix.sync.aligned.m8n8.x4.trans.shared.b16 {%0,%1,%2,%3}, [%4];"
                 : "=r"(r[0]), "=r"(r[1]), "=r"(r[2]), "=r"(r[3]) : "r"(addr));
}

static __device__ __forceinline__ void mma16816h(float* c, const uint32_t* a,
                                                 uint32_t b0, uint32_t b1) {
    asm volatile("mma.sync.aligned.m16n8k16.row.col.f32.f16.f16.f32 "
                 "{%0,%1,%2,%3}, {%4,%5,%6,%7}, {%8,%9}, {%0,%1,%2,%3};"
                 : "+f"(c[0]), "+f"(c[1]), "+f"(c[2]), "+f"(c[3])
                 : "r"(a[0]), "r"(a[1]), "r"(a[2]), "r"(a[3]), "r"(b0), "r"(b1));
}

static __device__ __forceinline__ uint32_t pack_f16(float a, float b) {
    uint32_t r;
    asm("cvt.rn.f16x2.f32 %0, %1, %2;" : "=r"(r) : "f"(b), "f"(a));
    return r;
}
static __device__ __forceinline__ ushort_t f16(float x) {
    ushort_t r;
    asm("cvt.rn.f16.f32 %0, %1;" : "=h"(r) : "f"(x));
    return r;
}

static __device__ __forceinline__ float ex2(float x) {
    float r;
    asm("ex2.approx.f32 %0, %1;" : "=f"(r) : "f"(x));
    return r;
}

#define CP_ASYNC(dst, src) \
    asm volatile("cp.async.cg.shared.global [%0], [%1], 16;" \
                 :: "r"(dst), "l"(src) : "memory")
#define CP_COMMIT() asm volatile("cp.async.commit_group;" ::: "memory")
#define CP_WAIT2() asm volatile("cp.async.wait_group 2;" ::: "memory")
#define CP_WAIT1() asm volatile("cp.async.wait_group 1;" ::: "memory")
#define CP_WAIT0() asm volatile("cp.async.wait_group 0;" ::: "memory")

// ---------------- merged fp32 -> fp16 convert --------------------------------
#define CV_N0 (BT * HID / 4)
#define CV_N1 (HID * HID / 4)
#define CV_N2 (NKV * HD * HID / 4)
#define CV_N3 (NKV * HD * HID / 4)
#define CV_N4 (HID * HID / 4)
#define CV_TOT (CV_N0 + CV_N1 + CV_N2 + CV_N3 + CV_N4)

__global__ __launch_bounds__(256) void cvt_all(
    const float* __restrict__ h,  const float* __restrict__ wq,
    const float* __restrict__ wk, const float* __restrict__ wv,
    const float* __restrict__ wo) {
    int i = blockIdx.x * blockDim.x + threadIdx.x;
    const float* src;
    ushort_t* dst;
    if (i < CV_N0)                      { src = h;  dst = g_hf; }
    else if ((i -= CV_N0) < CV_N1)      { src = wq; dst = g_wqf; }
    else if ((i -= CV_N1) < CV_N2)      { src = wk; dst = g_wkf; }
    else if ((i -= CV_N2) < CV_N3)      { src = wv; dst = g_wvf; }
    else if ((i -= CV_N3) < CV_N4)      { src = wo; dst = g_wof; }
    else return;
    float4 f = ((const float4*)src)[i];
    ((uint2*)dst)[i] = make_uint2(pack_f16(f.x, f.y), pack_f16(f.z, f.w));
}

// =============== fp16 mma.sync GEMM, k32 chunks, 4-stage pipeline ===========
// MODE 0: O projection, fp32 C store (grid 16x32).
// MODE 1: merged QKV (grid 24x32): x<16 Q(rope+scale), 16-19 K(rope), 20-23 V.
#define G_ROWB 80
#define G_TILE 10240
#define G_STAGE_B (2 * G_TILE)              // 20480
#define G_SMEM (4 * G_STAGE_B + 128)        // 82048

template<int MODE>
__global__ __launch_bounds__(256, 2) void gemm_fused(
    const ushort_t* __restrict__ A,
    const ushort_t* __restrict__ B1,
    const ushort_t* __restrict__ B2,
    const ushort_t* __restrict__ B3,
    float* __restrict__ C,
    const float* __restrict__ cosp, const float* __restrict__ sinp,
    int K) {
    extern __shared__ char dsm[];
    const uint32_t tile = (smem_u32(dsm) + 127u) & ~127u;

    const int tid = threadIdx.x;
    const int wid = tid >> 5;
    const int lane = tid & 31;
    const int wm = wid & 3;
    const int wn = wid >> 2;

    const bool isQ = (MODE == 0) || (blockIdx.x < 16);
    const bool isV = (MODE == 1) && (blockIdx.x >= 20);
    const int bnx = (MODE == 0) ? (int)blockIdx.x
                   : (blockIdx.x < 16 ? (int)blockIdx.x
                      : (isV ? (int)blockIdx.x - 20 : (int)blockIdx.x - 16));
    const int bm = blockIdx.y * 128;
    const int bn = bnx * 128;
    const ushort_t* Bm = (MODE == 0) ? B1
                        : (blockIdx.x < 16 ? B1 : (isV ? B3 : B2));

    const int row = tid >> 1;
    const int half = tid & 1;
    const ushort_t* pA = A  + (size_t)(bm + row) * K + half * 16;
    const ushort_t* pB = Bm + (size_t)(bn + row) * K + half * 16;
    const uint32_t s_row = (uint32_t)(row * G_ROWB + half * 32);

    const int r8 = lane & 7, sub = lane >> 3;
    const uint32_t a_off = (uint32_t)((wm * 32 + r8 + (sub & 1) * 8) * G_ROWB +
                                      (sub >> 1) * 16);
    const uint32_t b_off = (uint32_t)((wn * 64 + r8 + (sub >> 1) * 8) * G_ROWB +
                                      (sub & 1) * 16);

    float acc[2][8][4];
#pragma unroll
    for (int i = 0; i < 2; i++)
#pragma unroll
        for (int j = 0; j < 8; j++)
#pragma unroll
            for (int q = 0; q < 4; q++) acc[i][j][q] = 0.f;

    const int nch = K >> 5;

#define G_ISSUE(chunk, sb) do {                                               \
    const int _k0 = (chunk) << 5;                                             \
    CP_ASYNC((sb) + s_row,               pA + _k0);                           \
    CP_ASYNC((sb) + s_row + 16,          pA + _k0 + 8);                       \
    CP_ASYNC((sb) + G_TILE + s_row,      pB + _k0);                           \
    CP_ASYNC((sb) + G_TILE + s_row + 16, pB + _k0 + 8);                       \
} while (0)

    G_ISSUE(0, tile);                  CP_COMMIT();
    G_ISSUE(1, tile + G_STAGE_B);      CP_COMMIT();
    G_ISSUE(2, tile + 2 * G_STAGE_B);  CP_COMMIT();

    int st = 0;                         // i % 4
    for (int i = 0; i < nch; i++) {
        const uint32_t cur = tile + (uint32_t)st * G_STAGE_B;
        if (i + 2 < nch)      { CP_WAIT2(); }
        else if (i + 1 < nch) { CP_WAIT1(); }
        else                  { CP_WAIT0(); }
        __syncthreads();
        // issue chunk i+3 into stage (i+3)%4 == (i-1)%4 — its consumer
        // (compute i-1) finished before the barrier above.
        if (i + 3 < nch) {
            int st3 = st + 3; if (st3 >= 4) st3 -= 4;
            G_ISSUE(i + 3, tile + (uint32_t)st3 * G_STAGE_B);
            CP_COMMIT();
        }

#pragma unroll
        for (int ks = 0; ks < 2; ks++) {
            uint32_t ah[8];
            const uint32_t ka = cur + a_off + ks * 32;
            ldm4(ah,     ka);
            ldm4(ah + 4, ka + 16 * G_ROWB);
#pragma unroll
            for (int g = 0; g < 4; g++) {
                uint32_t bh[4];
                ldm4(bh, cur + G_TILE + b_off + ks * 32 + g * (16 * G_ROWB));
#pragma unroll
                for (int ms = 0; ms < 2; ms++) {
                    mma16816h(acc[ms][2 * g],     ah + 4 * ms, bh[0], bh[1]);
                    mma16816h(acc[ms][2 * g + 1], ah + 4 * ms, bh[2], bh[3]);
                }
            }
        }
        if (++st == 4) st = 0;
    }
#undef G_ISSUE

    // ---------------- epilogues ----------------
    const int trow = lane >> 2;
    const int tcol = (lane & 3) * 2;

    if (MODE == 0) {
#pragma unroll
        for (int ms = 0; ms < 2; ms++) {
#pragma unroll
            for (int nf = 0; nf < 8; nf++) {
                const int r = bm + wm * 32 + ms * 16 + trow;
                const int c = bn + wn * 64 + nf * 8 + tcol;
                *(float2*)(C + (size_t)r * HID + c) =
                    make_float2(acc[ms][nf][0], acc[ms][nf][1]);
                *(float2*)(C + (size_t)(r + 8) * HID + c) =
                    make_float2(acc[ms][nf][2], acc[ms][nf][3]);
            }
        }
    } else {
        const int head = (bn + wn * 64) >> 6;
        const int nheads = isQ ? NH : NKV;
        const float sc = isQ ? (0.125f * 1.4426950408889634f) : 1.0f;
        ushort_t* gf = isQ ? g_qf : (isV ? g_vf : g_kf);
#pragma unroll
        for (int ms = 0; ms < 2; ms++) {
#pragma unroll
            for (int q2 = 0; q2 < 2; q2++) {
                const int token = bm + wm * 32 + ms * 16 + trow + q2 * 8;
                const int bb = token >> 11;
                const int tt = token & (Tdim - 1);
                const size_t obase =
                    ((size_t)(bb * nheads + head) * Tdim + tt) * HD;
                if (isV) {
#pragma unroll
                    for (int nf = 0; nf < 8; nf++) {
#pragma unroll
                        for (int qc = 0; qc < 2; qc++) {
                            const int d = nf * 8 + tcol + qc;
                            gf[obase + d] = f16(acc[ms][nf][q2 * 2 + qc]);
                        }
                    }
                } else {
#pragma unroll
                    for (int nf = 0; nf < 4; nf++) {
#pragma unroll
                        for (int qc = 0; qc < 2; qc++) {
                            const int d = nf * 8 + tcol + qc;   // 0..31
                            float x1 = acc[ms][nf][q2 * 2 + qc];
                            float x2 = acc[ms][nf + 4][q2 * 2 + qc];
                            float c = cosp[(size_t)token * HD + d];
                            float s = sinp[(size_t)token * HD + d];
                            gf[obase + d]      = f16((x1 * c - x2 * s) * sc);
                            gf[obase + d + 32] = f16((x2 * c + x1 * s) * sc);
                        }
                    }
                }
            }
        }
    }
}

// ---------------- Flash attention (fp16, 3-stage cp.async pipeline) ---------
// (exact R15 version — proven 527 µs configuration)
#define FB 144
#define FA_SMEM (4 * 18432)   // 73728

__global__ __launch_bounds__(256, 2) void flash_mma() {
    extern __shared__ ushort_t fsm[];
    const uint32_t s0 = smem_u32(fsm);
    const uint32_t sQ = s0;

    const int tid = threadIdx.x;
    const int lane = tid & 31;
    const int w = tid >> 5;
    const int qtile = (int)gridDim.x - 1 - (int)blockIdx.x;  // big first
    const int bh = blockIdx.y;
    const int b = bh / NH;
    const int h = bh % NH;
    const int kvh = h / (NH / NKV);

    const ushort_t* qp = g_qf + ((size_t)bh * Tdim + qtile * 128) * HD;
    const size_t kvbase = (size_t)(b * NKV + kvh) * Tdim * HD;
    const ushort_t* pk = g_kf + kvbase;
    const ushort_t* pv = g_vf + kvbase;

    const uint32_t d0 = (uint32_t)((tid >> 3) * FB + (tid & 7) * 16);
    const uint32_t d1 = (uint32_t)(((tid + 256) >> 3) * FB + (tid & 7) * 16);
    const uint32_t g0 = (uint32_t)((tid >> 3) * HD + (tid & 7) * 8);
    const uint32_t g1 = (uint32_t)(((tid + 256) >> 3) * HD + (tid & 7) * 8);

#define FA_ISSUE(kt, stg) do {                                                \
    const uint32_t _sb = s0 + 18432 + (uint32_t)(stg) * 18432;                \
    const size_t _go = (size_t)(kt) * 64 * HD;                                \
    CP_ASYNC(_sb + d0,        pk + _go + g0);                                 \
    CP_ASYNC(_sb + d1,        pk + _go + g1);                                 \
    CP_ASYNC(_sb + 9216 + d0, pv + _go + g0);                                 \
    CP_ASYNC(_sb + 9216 + d1, pv + _go + g1);                                 \
} while (0)

    FA_ISSUE(0, 0); CP_COMMIT();
    FA_ISSUE(1, 1); CP_COMMIT();

    // stage Q (128x64 fp16)
#pragma unroll
    for (int j = 0; j < 4; j++) {
        const int idx = tid + j * 256;
        const int qr = idx >> 3;
        const int qc = idx & 7;
        *(uint4*)(fsm + qr * 72 + qc * 8) = *(const uint4*)(qp + qr * HD + qc * 8);
    }

    const int r8 = lane & 7, sub = lane >> 3;
    const uint32_t a_off = (uint32_t)((w * 16 + r8 + ((sub & 1) << 3)) * FB +
                                      ((sub >> 1) << 4));
    const uint32_t b_off = (uint32_t)((r8 + ((sub >> 1) << 3)) * FB +
                                      ((sub & 1) << 4));
    const uint32_t v_off = (uint32_t)(((lane & 8) + (lane & 7)) * FB +
                                      (lane >> 4) * 16);

    float m0 = -1e30f, m1 = -1e30f, l0 = 0.f, l1 = 0.f;
    float o[8][4];
#pragma unroll
    for (int t = 0; t < 8; t++)
#pragma unroll
        for (int e = 0; e < 4; e++) o[t][e] = 0.f;

    const int ktmax = 2 * qtile + 1;
    int st = 0;                           // kt % 3
    for (int kt = 0; kt <= ktmax; kt++) {
        const uint32_t stgK = s0 + 18432 + (uint32_t)st * 18432;
        const uint32_t stgV = stgK + 9216;
        if (kt < ktmax) { CP_WAIT1(); } else { CP_WAIT0(); }
        __syncthreads();
        if (kt + 2 <= ktmax) {
            int st2 = st + 2; if (st2 >= 3) st2 -= 3;
            FA_ISSUE(kt + 2, st2);
            CP_COMMIT();
        }

        // last tile: warps 0-3 fully above diagonal -> exact no-op
        if (kt < ktmax || w >= 4) {
            float sa[8][4];
#pragma unroll
            for (int t = 0; t < 8; t++)
#pragma unroll
                for (int e = 0; e < 4; e++) sa[t][e] = 0.f;

#pragma unroll
            for (int ks = 0; ks < 4; ks++) {
                uint32_t aq[4];
                ldm4(aq, sQ + a_off + ks * 32);
#pragma unroll
                for (int g = 0; g < 4; g++) {
                    uint32_t kb[4];
                    ldm4(kb, stgK + b_off + ks * 32 + g * (16 * FB));
                    mma16816h(sa[2 * g],     aq, kb[0], kb[1]);
                    mma16816h(sa[2 * g + 1], aq, kb[2], kb[3]);
                }
            }

            if (kt >= 2 * qtile) {
                const int row0 = qtile * 128 + w * 16 + (lane >> 2);
                const int cb = kt * 64 + (lane & 3) * 2;
#pragma unroll
                for (int t = 0; t < 8; t++) {
                    const int c0 = cb + t * 8;
                    if (c0 > row0)         sa[t][0] = -1e30f;
                    if (c0 + 1 > row0)     sa[t][1] = -1e30f;
                    if (c0 > row0 + 8)     sa[t][2] = -1e30f;
                    if (c0 + 1 > row0 + 8) sa[t][3] = -1e30f;
                }
            }

            float rm0 = -1e30f, rm1 = -1e30f;
#pragma unroll
            for (int t = 0; t < 8; t++) {
                rm0 = fmaxf(rm0, fmaxf(sa[t][0], sa[t][1]));
                rm1 = fmaxf(rm1, fmaxf(sa[t][2], sa[t][3]));
            }
            rm0 = fmaxf(rm0, __shfl_xor_sync(0xffffffffu, rm0, 1));
            rm0 = fmaxf(rm0, __shfl_xor_sync(0xffffffffu, rm0, 2));
            rm1 = fmaxf(rm1, __shfl_xor_sync(0xffffffffu, rm1, 1));
            rm1 = fmaxf(rm1, __shfl_xor_sync(0xffffffffu, rm1, 2));
            const float mn0 = fmaxf(m0, rm0);
            const float mn1 = fmaxf(m1, rm1);
            const float al0 = ex2(m0 - mn0);
            const float al1 = ex2(m1 - mn1);
            m0 = mn0; m1 = mn1;
            float rs0 = 0.f, rs1 = 0.f;
#pragma unroll
            for (int t = 0; t < 8; t++) {
                sa[t][0] = ex2(sa[t][0] - mn0);
                sa[t][1] = ex2(sa[t][1] - mn0);
                sa[t][2] = ex2(sa[t][2] - mn1);
                sa[t][3] = ex2(sa[t][3] - mn1);
                rs0 += sa[t][0] + sa[t][1];
                rs1 += sa[t][2] + sa[t][3];
            }
            rs0 += __shfl_xor_sync(0xffffffffu, rs0, 1);
            rs0 += __shfl_xor_sync(0xffffffffu, rs0, 2);
            rs1 += __shfl_xor_sync(0xffffffffu, rs1, 1);
            rs1 += __shfl_xor_sync(0xffffffffu, rs1, 2);
            l0 = l0 * al0 + rs0;
            l1 = l1 * al1 + rs1;
#pragma unroll
            for (int t = 0; t < 8; t++) {
                o[t][0] *= al0; o[t][1] *= al0;
                o[t][2] *= al1; o[t][3] *= al1;
            }

#pragma unroll
            for (int kc = 0; kc < 4; kc++) {
                const int t0 = 2 * kc, t1 = 2 * kc + 1;
                uint32_t ap[4];
                ap[0] = pack_f16(sa[t0][0], sa[t0][1]);
                ap[1] = pack_f16(sa[t0][2], sa[t0][3]);
                ap[2] = pack_f16(sa[t1][0], sa[t1][1]);
                ap[3] = pack_f16(sa[t1][2], sa[t1][3]);
#pragma unroll
                for (int tp = 0; tp < 4; tp++) {
                    uint32_t vb[4];
                    ldm4t(vb, stgV + v_off + kc * (16 * FB) + tp * 32);
                    mma16816h(o[2 * tp],     ap, vb[0], vb[1]);
                    mma16816h(o[2 * tp + 1], ap, vb[2], vb[3]);
                }
            }
        }
        if (++st == 3) st = 0;
    }
#undef FA_ISSUE

    // epilogue: normalize + fp16 write for the O projection
    const float inv0 = 1.0f / l0;
    const float inv1 = 1.0f / l1;
    const int row0 = qtile * 128 + w * 16 + (lane >> 2);
    const int colb = (lane & 3) * 2;
#pragma unroll
    for (int t = 0; t < 8; t++) {
        const int c = h * HD + t * 8 + colb;
        const size_t i0 = ((size_t)b * Tdim + row0) * (NH * HD) + c;
        const size_t i1 = ((size_t)b * Tdim + row0 + 8) * (NH * HD) + c;
        *(uint32_t*)(g_of + i0) = pack_f16(o[t][0] * inv0, o[t][1] * inv0);
        *(uint32_t*)(g_of + i1) = pack_f16(o[t][2] * inv1, o[t][3] * inv1);
    }
}

// ---------------- launch ----------------------------------------------------
extern "C" void kernel_launch(void* const* d_in, const int* in_sizes, int n_in,
                              void* d_out, int out_size) {
    const float* hidden = (const float*)d_in[0];
    const float* cosp   = (const float*)d_in[1];
    const float* sinp   = (const float*)d_in[2];
    const float* wq     = (const float*)d_in[3];
    const float* wk     = (const float*)d_in[4];
    const float* wv     = (const float*)d_in[5];
    const float* wo     = (const float*)d_in[6];
    float* out = (float*)d_out;

    ushort_t *hf, *wqf, *wkf, *wvf, *wof, *of;
    cudaGetSymbolAddress((void**)&hf,  g_hf);
    cudaGetSymbolAddress((void**)&wqf, g_wqf);
    cudaGetSymbolAddress((void**)&wkf, g_wkf);
    cudaGetSymbolAddress((void**)&wvf, g_wvf);
    cudaGetSymbolAddress((void**)&wof, g_wof);
    cudaGetSymbolAddress((void**)&of,  g_of);

    cudaFuncSetAttribute(gemm_fused<0>, cudaFuncAttributeMaxDynamicSharedMemorySize, G_SMEM);
    cudaFuncSetAttribute(gemm_fused<1>, cudaFuncAttributeMaxDynamicSharedMemorySize, G_SMEM);
    cudaFuncSetAttribute(flash_mma, cudaFuncAttributeMaxDynamicSharedMemorySize, FA_SMEM);

    // merged fp32 -> fp16 converts
    cvt_all<<<(CV_TOT + 255) / 256, 256>>>(hidden, wq, wk, wv, wo);

    // merged Q/K/V projections (Q: rope+scale, K: rope, V: plain) -> fp16
    gemm_fused<1><<<dim3(24, 32), 256, G_SMEM>>>(
        hf, wqf, wkf, wvf, nullptr, cosp, sinp, HID);

    // Flash attention (fp16 tensor cores)
    flash_mma<<<dim3(Tdim / 128, Bdim * NH), 256, FA_SMEM>>>();

    // Output projection (fp16, fp32 epilogue)
    gemm_fused<0><<<dim3(16, 32), 256, G_SMEM>>>(
        of, wof, nullptr, nullptr, out, nullptr, nullptr, HID);
}